// round 9
// baseline (speedup 1.0000x reference)
#include <cuda_runtime.h>
#include <math.h>

#define BLOCK 256
#define MAX_BLOCKS 8192

__device__ float g_partials[MAX_BLOCKS];
__device__ unsigned int g_count = 0;

// Antiderivative of clamp(x, -hw, hw):  G(x) = 0.5*clamp(x)^2 + hw*max(|x|-hw, 0)
__device__ __forceinline__ float boxG(float x, float hw) {
    float c = fminf(fmaxf(x, -hw), hw);
    float e = fmaxf(fabsf(x) - hw, 0.0f);
    return fmaf(hw, e, 0.5f * c * c);
}

// One box2 edge's contribution to the clamp-curve area integral.
__device__ __forceinline__ float edge_int(float Px, float Py,
                                          float Dx, float Dy,
                                          float rdy, float kxy,
                                          float hw, float hh) {
    float tA = (hh - Py) * rdy;
    float tB = (-hh - Py) * rdy;
    float A = __saturatef(fminf(tA, tB));
    float B = __saturatef(fmaxf(tA, tB));
    float xA = fmaf(A, Dx, Px);
    float xB = fmaf(B, Dx, Px);
    return kxy * (boxG(xB, hw) - boxG(xA, hw));
}

// rcp with degeneracy clamp: ±inf -> ±1e8, sign preserved.
__device__ __forceinline__ float safe_rcp(float d) {
    float r = __frcp_rn(d);
    return fminf(fmaxf(r, -1e8f), 1e8f);
}

// iou^3 for one box pair, fully branchless.
__device__ __forceinline__ float iou3(float x1, float y1, float w1f, float h1f, float a1,
                                      float x2, float y2, float w2f, float h2f, float a2) {
    float area1 = w1f * h1f;
    float area2 = w2f * h2f;

    float s1, c1;
    __sincosf(a1, &s1, &c1);
    float rx = x2 - x1, ry = y2 - y1;
    float cx = rx * c1 + ry * s1;
    float cy = -rx * s1 + ry * c1;
    float sr, cr;
    __sincosf(a2 - a1, &sr, &cr);
    float hw2 = 0.5f * w2f, hh2 = 0.5f * h2f;
    float e1x = hw2 * cr, e1y = hw2 * sr;
    float e2x = -hh2 * sr, e2y = hh2 * cr;

    float q0x = cx - e1x - e2x, q0y = cy - e1y - e2y;
    float q1x = cx + e1x - e2x, q1y = cy + e1y - e2y;
    float q2x = cx + e1x + e2x, q2y = cy + e1y + e2y;
    float q3x = cx - e1x + e2x, q3y = cy - e1y + e2y;

    float D1x = 2.0f * e1x, D1y = 2.0f * e1y;
    float D2x = 2.0f * e2x, D2y = 2.0f * e2y;
    float r1x = safe_rcp(D1x), r1y = safe_rcp(D1y);
    float r2x = safe_rcp(D2x), r2y = safe_rcp(D2y);
    float k1 = D1y * r1x;  // shared by edges 0 & 2 (signs cancel)
    float k2 = D2y * r2x;  // shared by edges 1 & 3

    float hw = 0.5f * w1f, hh = 0.5f * h1f;

    float i0 = edge_int(q0x, q0y,  D1x,  D1y,  r1y, k1, hw, hh);
    float i1 = edge_int(q1x, q1y,  D2x,  D2y,  r2y, k2, hw, hh);
    float i2 = edge_int(q2x, q2y, -D1x, -D1y, -r1y, k1, hw, hh);
    float i3 = edge_int(q3x, q3y, -D2x, -D2y, -r2y, k2, hw, hh);

    float inter = fabsf((i0 + i2) + (i1 + i3));
    float iou = __fdividef(inter, area1 + area2 - inter);
    iou = fmaxf(iou, 1e-6f);
    return iou * iou * iou;
}

__global__ void __launch_bounds__(BLOCK)
rot_iou_loss_kernel(const float* __restrict__ pred,
                    const float* __restrict__ tgt,
                    float* __restrict__ out,
                    int n, int nblocks, float inv_n) {
    int tid = threadIdx.x;
    int j = blockIdx.x * BLOCK + tid;
    int npairs = n >> 1;

    float s = 0.0f;
    if (j < npairs) {
        // 10 contiguous, 8B-aligned floats per array -> 5 x LDG.64 each.
        const float2* P = reinterpret_cast<const float2*>(pred) + 5ll * j;
        const float2* T = reinterpret_cast<const float2*>(tgt) + 5ll * j;
        float2 P0 = P[0], P1 = P[1], P2 = P[2], P3 = P[3], P4 = P[4];
        float2 T0 = T[0], T1 = T[1], T2 = T[2], T3 = T[3], T4 = T[4];

        // two independent branchless chains -> ptxas interleaves (ILP-2)
        float sa = iou3(P0.x, P0.y, P1.x, P1.y, P2.x,
                        T0.x, T0.y, T1.x, T1.y, T2.x);
        float sb = iou3(P2.y, P3.x, P3.y, P4.x, P4.y,
                        T2.y, T3.x, T3.y, T4.x, T4.y);
        s = sa + sb;
    }
    // odd-n tail element (not taken for even n)
    if ((n & 1) && j == 0) {
        const float* p = pred + 5ll * (n - 1);
        const float* t = tgt + 5ll * (n - 1);
        s += iou3(p[0], p[1], p[2], p[3], p[4], t[0], t[1], t[2], t[3], t[4]);
    }

    // in-block reduction (fixed order -> deterministic)
    __shared__ float sdata[BLOCK / 32];
    float v = s;
#pragma unroll
    for (int off = 16; off > 0; off >>= 1)
        v += __shfl_down_sync(0xFFFFFFFFu, v, off);
    if ((tid & 31) == 0) sdata[tid >> 5] = v;
    __syncthreads();
    if (tid < 32) {
        float w = (tid < BLOCK / 32) ? sdata[tid] : 0.0f;
#pragma unroll
        for (int off = 4; off > 0; off >>= 1)
            w += __shfl_down_sync(0xFFFFFFFFu, w, off);
        if (tid == 0) g_partials[blockIdx.x] = w;
    }

    // last-block final reduction (deterministic index-order sum)
    __shared__ bool is_last;
    __threadfence();
    if (tid == 0) {
        unsigned int c = atomicAdd(&g_count, 1u);
        is_last = (c == (unsigned int)nblocks - 1u);
    }
    __syncthreads();
    if (is_last) {
        __shared__ double dd[BLOCK];
        double acc = 0.0;
        for (int k = tid; k < nblocks; k += BLOCK) acc += (double)g_partials[k];
        dd[tid] = acc;
        __syncthreads();
#pragma unroll
        for (int st = BLOCK / 2; st > 0; st >>= 1) {
            if (tid < st) dd[tid] += dd[tid + st];
            __syncthreads();
        }
        if (tid == 0) {
            // mean(1 - iou^3) = 1 - sum(iou^3)/n
            out[0] = (float)(1.0 - dd[0] * (double)inv_n);
            g_count = 0;  // reset for next graph replay
        }
    }
}

extern "C" void kernel_launch(void* const* d_in, const int* in_sizes, int n_in,
                              void* d_out, int out_size) {
    const float* pred = (const float*)d_in[0];
    const float* tgt  = (const float*)d_in[1];
    int n = in_sizes[0] / 5;
    int npairs = n >> 1;
    int nthreads = npairs > 0 ? npairs : 1;
    int nblocks = (nthreads + BLOCK - 1) / BLOCK;
    rot_iou_loss_kernel<<<nblocks, BLOCK>>>(pred, tgt, (float*)d_out,
                                            n, nblocks, 1.0f / (float)n);
}

// round 10
// speedup vs baseline: 1.2909x; 1.2909x over previous
#include <cuda_runtime.h>
#include <math.h>

#define BLOCK 256
#define MAX_BLOCKS 8192

__device__ float g_partials[MAX_BLOCKS];
__device__ unsigned int g_count = 0;

// rcp with degeneracy clamp (sign-preserving): only needed where the
// reciprocal multiplies a possibly-zero difference (k = |Dy|*rdx).
__device__ __forceinline__ float safe_rcp(float d) {
    float r = __frcp_rn(d);
    return fminf(fmaxf(r, -1e8f), 1e8f);
}

// Per-edge G2-difference. G2(x) = m^2 + 2*hw*|x| - hw^2, m = max(hw-|x|,0)
// (2x the clamp antiderivative); the -hw^2 cancels in the difference.
// Unsorted t-window: the sign flip vs the sorted form is exactly sign(Dy),
// absorbed by using |Dy| in k.
__device__ __forceinline__ float edge_g2diff(float Px, float Py, float Dx,
                                             float rdy, float hw, float w1,
                                             float hh) {
    float tA = __saturatef((hh - Py) * rdy);   // NaN/inf -> [0,1]
    float tB = __saturatef((-hh - Py) * rdy);
    float xA = fmaf(tA, Dx, Px);
    float xB = fmaf(tB, Dx, Px);
    float mA = fmaxf(hw - fabsf(xA), 0.0f);
    float mB = fmaxf(hw - fabsf(xB), 0.0f);
    float gA = fmaf(mA, mA, w1 * fabsf(xA));   // 2*hw == w1
    float gB = fmaf(mB, mB, w1 * fabsf(xB));
    return gA - gB;
}

// iou^3 for one rotated-box pair; fully branchless.
__device__ __forceinline__ float iou3(float x1, float y1, float w1, float h1, float a1,
                                      float x2, float y2, float w2, float h2, float a2) {
    float area12 = fmaf(w1, h1, w2 * h2);

    float s1, c1;
    __sincosf(a1, &s1, &c1);
    float rx = x2 - x1, ry = y2 - y1;
    float cx = rx * c1 + ry * s1;
    float cy = ry * c1 - rx * s1;
    float sr, cr;
    __sincosf(a2 - a1, &sr, &cr);

    // full edge vectors of box2 in box1 frame
    float D1x = w2 * cr, D1y = w2 * sr;
    float D2x = -h2 * sr, D2y = h2 * cr;
    float e1x = 0.5f * D1x, e1y = 0.5f * D1y;
    float e2x = 0.5f * D2x, e2y = 0.5f * D2y;

    // corners (CCW)
    float ux = cx - e1x, vx = cx + e1x;
    float uy = cy - e1y, vy = cy + e1y;
    float q0x = ux - e2x, q0y = uy - e2y;
    float q1x = vx - e2x, q1y = vy - e2y;
    float q2x = vx + e2x, q2y = vy + e2y;
    float q3x = ux + e2x, q3y = uy + e2y;

    float r1x = safe_rcp(D1x), r2x = safe_rcp(D2x);
    float r1y = __frcp_rn(D1y), r2y = __frcp_rn(D2y);
    float k1 = fabsf(D1y) * r1x;   // edges 0 & 2
    float k2 = fabsf(D2y) * r2x;   // edges 1 & 3

    float hw = 0.5f * w1, hh = 0.5f * h1;

    float d0 = edge_g2diff(q0x, q0y,  D1x,  r1y, hw, w1, hh);
    float d1 = edge_g2diff(q1x, q1y,  D2x,  r2y, hw, w1, hh);
    float d2 = edge_g2diff(q2x, q2y, -D1x, -r1y, hw, w1, hh);
    float d3 = edge_g2diff(q3x, q3y, -D2x, -r2y, hw, w1, hh);

    // S = 2 * intersection area; iou = (S/2)/(area12 - S/2) = S/(2*area12 - S)
    float S = fabsf(fmaf(k1, d0 - d2, k2 * (d1 - d3)));
    float denom = fmaf(2.0f, area12, -S);
    float iou = fmaxf(__fdividef(S, denom), 1e-6f);
    return iou * iou * iou;
}

// iou^3 for the adjacent element pair stored in 5 float2s.
__device__ __forceinline__ float iou3_pair(const float2* __restrict__ P,
                                           const float2* __restrict__ T) {
    float2 P0 = P[0], P1 = P[1], P2 = P[2], P3 = P[3], P4 = P[4];
    float2 T0 = T[0], T1 = T[1], T2 = T[2], T3 = T[3], T4 = T[4];
    float sa = iou3(P0.x, P0.y, P1.x, P1.y, P2.x,
                    T0.x, T0.y, T1.x, T1.y, T2.x);
    float sb = iou3(P2.y, P3.x, P3.y, P4.x, P4.y,
                    T2.y, T3.x, T3.y, T4.x, T4.y);
    return sa + sb;
}

__global__ void __launch_bounds__(BLOCK)
rot_iou_loss_kernel(const float* __restrict__ pred,
                    const float* __restrict__ tgt,
                    float* __restrict__ out,
                    int n, int nblocks, float inv_n) {
    int tid = threadIdx.x;
    int j = blockIdx.x * BLOCK + tid;
    int quarter = n >> 2;   // threads; each handles 2 pair-blocks = 4 elements

    float s = 0.0f;
    if (j < quarter) {
        const float2* Pb = reinterpret_cast<const float2*>(pred);
        const float2* Tb = reinterpret_cast<const float2*>(tgt);
        // four independent branchless chains -> ILP-4
        float sA = iou3_pair(Pb + 5ll * j, Tb + 5ll * j);
        float sB = iou3_pair(Pb + 5ll * (j + quarter), Tb + 5ll * (j + quarter));
        s = sA + sB;
    }
    // tail: n mod 4 elements (none for n = 1e6)
    if (j == 0) {
        for (int e = quarter << 2; e < n; e++) {
            const float* p = pred + 5ll * e;
            const float* t = tgt + 5ll * e;
            s += iou3(p[0], p[1], p[2], p[3], p[4],
                      t[0], t[1], t[2], t[3], t[4]);
        }
    }

    // in-block reduction (fixed order -> deterministic)
    __shared__ float sdata[BLOCK / 32];
    float v = s;
#pragma unroll
    for (int off = 16; off > 0; off >>= 1)
        v += __shfl_down_sync(0xFFFFFFFFu, v, off);
    if ((tid & 31) == 0) sdata[tid >> 5] = v;
    __syncthreads();
    if (tid < 32) {
        float w = (tid < BLOCK / 32) ? sdata[tid] : 0.0f;
#pragma unroll
        for (int off = 4; off > 0; off >>= 1)
            w += __shfl_down_sync(0xFFFFFFFFu, w, off);
        if (tid == 0) g_partials[blockIdx.x] = w;
    }

    // last-block final reduction (deterministic index-order sum)
    __shared__ bool is_last;
    __threadfence();
    if (tid == 0) {
        unsigned int c = atomicAdd(&g_count, 1u);
        is_last = (c == (unsigned int)nblocks - 1u);
    }
    __syncthreads();
    if (is_last) {
        __shared__ double dd[BLOCK];
        double acc = 0.0;
        for (int k = tid; k < nblocks; k += BLOCK) acc += (double)g_partials[k];
        dd[tid] = acc;
        __syncthreads();
#pragma unroll
        for (int st = BLOCK / 2; st > 0; st >>= 1) {
            if (tid < st) dd[tid] += dd[tid + st];
            __syncthreads();
        }
        if (tid == 0) {
            // mean(1 - iou^3) = 1 - sum(iou^3)/n
            out[0] = (float)(1.0 - dd[0] * (double)inv_n);
            g_count = 0;  // reset for next graph replay
        }
    }
}

extern "C" void kernel_launch(void* const* d_in, const int* in_sizes, int n_in,
                              void* d_out, int out_size) {
    const float* pred = (const float*)d_in[0];
    const float* tgt  = (const float*)d_in[1];
    int n = in_sizes[0] / 5;
    int quarter = n >> 2;
    int nthreads = quarter > 0 ? quarter : 1;
    int nblocks = (nthreads + BLOCK - 1) / BLOCK;
    rot_iou_loss_kernel<<<nblocks, BLOCK>>>(pred, tgt, (float*)d_out,
                                            n, nblocks, 1.0f / (float)n);
}